// round 15
// baseline (speedup 1.0000x reference)
#include <cuda_runtime.h>
#include <cuda_fp16.h>
#include <math.h>
#include <stdint.h>

#define BDIM 16384
#define HDIM 512
#define NTAU 5
#define EPSV 1e-5f

// ---------------- scratch (static __device__: allocation-guard safe) --------
__device__ __half g_bufT[(size_t)BDIM * 3 * HDIM];   // fp16 raw T_concat
__device__ __half g_bufS[(size_t)BDIM * 3 * HDIM];   // fp16 raw S_concat
__device__ __half g_rawS[(size_t)BDIM * HDIM];       // fp16 raw s_next (pre-LN)
__device__ __half g_rawT[(size_t)BDIM * HDIM];       // fp16 raw t_next (pre-LN)
__device__ __half g_tfus[(size_t)BDIM * HDIM];       // fp16 T_fusion
__device__ __half g_Tr[(size_t)BDIM * HDIM];         // fp16 T_t
__device__ __half g_Sr[(size_t)BDIM * HDIM];         // fp16 S_t
__device__ __half g_Wtn_t[(size_t)HDIM * HDIM];      // transposed fp16 weights
__device__ __half g_Wsn_t[(size_t)HDIM * HDIM];
__device__ __half g_Wt_t[(size_t)3 * HDIM * HDIM];
__device__ __half g_Ws_t[(size_t)3 * HDIM * HDIM];

// ---------------- helpers ----------------------------------------------------
__device__ __forceinline__ uint32_t smem_u32(const void* p) {
    uint32_t a;
    asm("{ .reg .u64 t; cvta.to.shared.u64 t, %1; cvt.u32.u64 %0, t; }" : "=r"(a) : "l"(p));
    return a;
}
__device__ __forceinline__ float sigmoidf_(float x) {
    return 1.0f / (1.0f + __expf(-x));
}
__device__ __forceinline__ float4 ld_h4(const __half* p, size_t idx4) {
    const uint2 raw = reinterpret_cast<const uint2*>(p)[idx4];
    const float2 f01 = __half22float2(*reinterpret_cast<const __half2*>(&raw.x));
    const float2 f23 = __half22float2(*reinterpret_cast<const __half2*>(&raw.y));
    return make_float4(f01.x, f01.y, f23.x, f23.y);
}
#define CP16(s, g) asm volatile("cp.async.cg.shared.global [%0], [%1], 16;" :: "r"(s), "l"(g))
#define CP_COMMIT() asm volatile("cp.async.commit_group;" ::: "memory")
#define LDM_X4(r0, r1, r2, r3, ad) \
    asm volatile("ldmatrix.sync.aligned.m8n8.x4.shared.b16 {%0,%1,%2,%3}, [%4];" \
        : "=r"(r0), "=r"(r1), "=r"(r2), "=r"(r3) : "r"(ad))

// ---------------- merged prepass: 4 transposes + 2 fp32->fp16 converts ------
__global__ void prep_all(
    const float* __restrict__ W_sn, const float* __restrict__ W_tn,
    const float* __restrict__ W_t,  const float* __restrict__ W_s,
    const float* __restrict__ S,    const float* __restrict__ T,
    __half* __restrict__ O_sn, __half* __restrict__ O_tn,
    __half* __restrict__ O_t,  __half* __restrict__ O_s,
    __half* __restrict__ Sh,   __half* __restrict__ Th)
{
    const int z = blockIdx.z;
    if (z >= 4) {
        const float* in = (z == 4) ? S : T;
        __half* out     = (z == 4) ? Sh : Th;
        const int th = (blockIdx.y * 48 + blockIdx.x) * 1024 +
                       threadIdx.y * 32 + threadIdx.x;     // 0..786431
        constexpr int TOT4 = BDIM * HDIM / 4;              // 2097152
        #pragma unroll
        for (int i = 0; i < 3; ++i) {
            const int idx = th + i * 786432;
            if (idx < TOT4) {
                float4 v = reinterpret_cast<const float4*>(in)[idx];
                __half2* o2 = reinterpret_cast<__half2*>(out) + (size_t)idx * 2;
                o2[0] = __floats2half2_rn(v.x, v.y);
                o2[1] = __floats2half2_rn(v.z, v.w);
            }
        }
        return;
    }
    const float* W; __half* O; int N;
    if      (z == 0) { W = W_sn; O = O_sn; N = HDIM; }
    else if (z == 1) { W = W_tn; O = O_tn; N = HDIM; }
    else if (z == 2) { W = W_t;  O = O_t;  N = 3 * HDIM; }
    else             { W = W_s;  O = O_s;  N = 3 * HDIM; }
    if (blockIdx.x * 32 >= N) return;

    __shared__ float tile[32][33];
    const int x = blockIdx.x * 32 + threadIdx.x;   // n
    const int y = blockIdx.y * 32 + threadIdx.y;   // k
    tile[threadIdx.y][threadIdx.x] = W[(size_t)y * N + x];
    __syncthreads();
    const int xo = blockIdx.y * 32 + threadIdx.x;  // k
    const int yo = blockIdx.x * 32 + threadIdx.y;  // n
    O[(size_t)yo * HDIM + xo] = __float2half_rn(tile[threadIdx.x][threadIdx.y]);
}

// ---------------- fp16 mma.sync GEMM body ------------------------------------
// 128x64 CTA tile, 8 warps, warp tile 64x16 (m16n8k16), BK=32, 3-stage
// cp.async. 32 acc regs/thread -> ~80 regs -> 3 CTA/SM (24 warps).
__device__ __forceinline__ void gemm_body(
    const __half* __restrict__ A, const __half* __restrict__ Bt,
    const float* __restrict__ bias, __half* __restrict__ C, int N,
    int bx, int by, char* smem)
{
    constexpr int K = 512, BK = 32, NT = K / BK;   // 16 k-iters
    constexpr int LDB = 80;                        // bytes per row (32h + 8h pad)
    constexpr int TILEA = 128 * LDB;               // 10240 B
    constexpr int TILEB = 64 * LDB;                // 5120 B
    constexpr int STAGEB = TILEA + TILEB;          // 15360 B per stage
    const uint32_t sb = smem_u32(smem);

    const int tid  = threadIdx.x;
    const int wid  = tid >> 5;
    const int lane = tid & 31;
    const int wm   = wid & 1;      // 2 m-groups of 64
    const int wn   = wid >> 1;     // 4 n-groups of 16
    const int m0 = by * 128;
    const int n0 = bx * 64;

    // cp.async: A 128 rows x 64B (2 thr/row, 32B each); B 64 rows x 64B
    // (4 thr/row, 16B each)
    const int ra  = tid >> 1;          // 0..127
    const int ca  = tid & 1;
    const int rb  = tid >> 2;          // 0..63
    const int cb  = tid & 3;
    const __half* Ag = A  + (size_t)(m0 + ra) * K + ca * 16;
    const __half* Bg = Bt + (size_t)(n0 + rb) * K + cb * 8;
    const uint32_t srowA = (uint32_t)(ra * LDB + ca * 32);
    const uint32_t srowB = (uint32_t)(rb * LDB + cb * 16);

    auto load = [&](int kt) {
        const uint32_t sa = sb + (uint32_t)((kt % 3) * STAGEB);
        const __half* ag = Ag + kt * BK;
        const __half* bg = Bg + kt * BK;
        CP16(sa + srowA,      ag);
        CP16(sa + srowA + 16, ag + 8);
        CP16(sa + TILEA + srowB, bg);
        CP_COMMIT();
    };

    load(0);
    load(1);

    float acc[4][2][4];
    #pragma unroll
    for (int i = 0; i < 4; ++i)
        #pragma unroll
        for (int j = 0; j < 2; ++j)
            #pragma unroll
            for (int q = 0; q < 4; ++q) acc[i][j][q] = 0.f;

    const int r8 = lane & 7;
    const int g  = lane >> 3;
    const int ga = g & 1;
    const int gb = g >> 1;

    for (int kt = 0; kt < NT; ++kt) {
        if (kt < NT - 1) asm volatile("cp.async.wait_group 1;" ::: "memory");
        else             asm volatile("cp.async.wait_group 0;" ::: "memory");
        __syncthreads();
        if (kt + 2 < NT) load(kt + 2);

        const uint32_t st = sb + (uint32_t)((kt % 3) * STAGEB);

        #pragma unroll
        for (int ks = 0; ks < 2; ++ks) {
            uint32_t af[4][4];
            #pragma unroll
            for (int mi = 0; mi < 4; ++mi) {
                const uint32_t ad = st +
                    (uint32_t)((wm * 64 + mi * 16 + ga * 8 + r8) * LDB +
                               (ks * 16 + gb * 8) * 2);
                LDM_X4(af[mi][0], af[mi][1], af[mi][2], af[mi][3], ad);
            }
            uint32_t bfr[4];
            {
                const uint32_t bd = st + TILEA +
                    (uint32_t)((wn * 16 + gb * 8 + r8) * LDB +
                               (ks * 16 + ga * 8) * 2);
                LDM_X4(bfr[0], bfr[1], bfr[2], bfr[3], bd);
            }
            #pragma unroll
            for (int mi = 0; mi < 4; ++mi)
                #pragma unroll
                for (int ni = 0; ni < 2; ++ni) {
                    float* d = acc[mi][ni];
                    asm volatile(
                        "mma.sync.aligned.m16n8k16.row.col.f32.f16.f16.f32 "
                        "{%0,%1,%2,%3}, {%4,%5,%6,%7}, {%8,%9}, {%0,%1,%2,%3};"
                        : "+f"(d[0]), "+f"(d[1]), "+f"(d[2]), "+f"(d[3])
                        : "r"(af[mi][0]), "r"(af[mi][1]), "r"(af[mi][2]), "r"(af[mi][3]),
                          "r"(bfr[ni * 2]), "r"(bfr[ni * 2 + 1]));
                }
        }
    }

    const int gm   = lane >> 2;
    const int colq = (lane & 3) * 2;
    #pragma unroll
    for (int ni = 0; ni < 2; ++ni) {
        const int col = n0 + wn * 16 + ni * 8 + colq;
        const float b0 = bias[col], b1 = bias[col + 1];
        #pragma unroll
        for (int mi = 0; mi < 4; ++mi) {
            const int row = m0 + wm * 64 + mi * 16 + gm;
            *reinterpret_cast<__half2*>(C + (size_t)row * N + col) =
                __floats2half2_rn(acc[mi][ni][0] + b0, acc[mi][ni][1] + b1);
            *reinterpret_cast<__half2*>(C + (size_t)(row + 8) * N + col) =
                __floats2half2_rn(acc[mi][ni][2] + b0, acc[mi][ni][3] + b1);
        }
    }
}

// Single-GEMM launcher (T_concat): grid (N/64, 128)
__global__ void __launch_bounds__(256, 3) gemm_f16(
    const __half* __restrict__ A, const __half* __restrict__ Bt,
    const float* __restrict__ bias, __half* __restrict__ C, int N)
{
    extern __shared__ char smem[];
    gemm_body(A, Bt, bias, C, N, blockIdx.x, blockIdx.y, smem);
}

// Fused launcher: 5120 CTAs flat. [0,3072) S_concat (24 bx), [3072,4096)
// rawS (8 bx), [4096,5120) rawT (8 bx).
__global__ void __launch_bounds__(256, 3) gemm3_f16(
    const __half* __restrict__ Sr, const __half* __restrict__ Tr,
    const __half* __restrict__ Wsn, const __half* __restrict__ Wtn,
    const __half* __restrict__ Ws,
    const float* __restrict__ b_sn, const float* __restrict__ b_tn,
    const float* __restrict__ b_s,
    __half* __restrict__ rawS, __half* __restrict__ rawT,
    __half* __restrict__ bufS)
{
    extern __shared__ char smem[];
    const int id = blockIdx.x;
    if (id < 3072) {
        gemm_body(Sr, Ws, b_s, bufS, 3 * HDIM, id % 24, id / 24, smem);
    } else if (id < 4096) {
        const int l = id - 3072;
        gemm_body(Sr, Wsn, b_sn, rawS, HDIM, l & 7, l >> 3, smem);
    } else {
        const int l = id - 4096;
        gemm_body(Tr, Wtn, b_tn, rawT, HDIM, l & 7, l >> 3, smem);
    }
}

// ---------------- fused LN+LN+attention+gate, TWO rows per 128-thr block ----
__global__ void __launch_bounds__(128) ln2_attn_fusion(
    const __half* __restrict__ rawS, const __half* __restrict__ rawT,
    const float* __restrict__ g_sn, const float* __restrict__ be_sn,
    const float* __restrict__ g_tn, const float* __restrict__ be_tn,
    const float* __restrict__ T_t,  const float* __restrict__ t_att,
    const float* __restrict__ s_att, __half* __restrict__ T_fusion)
{
    const int tid = threadIdx.x;
    const int lane = tid & 31, w = tid >> 5;
    size_t off4[2];
    off4[0] = ((size_t)(blockIdx.x * 2) * HDIM) >> 2;
    off4[1] = off4[0] + (HDIM >> 2);

    float4 vs[2], vt[2];
    #pragma unroll
    for (int q = 0; q < 2; ++q) {
        vs[q] = ld_h4(rawS, off4[q] + tid);
        vt[q] = ld_h4(rawT, off4[q] + tid);
    }

    float red8[8];
    #pragma unroll
    for (int q = 0; q < 2; ++q) {
        red8[q * 4 + 0] = vs[q].x + vs[q].y + vs[q].z + vs[q].w;
        red8[q * 4 + 1] = fmaf(vs[q].x, vs[q].x, fmaf(vs[q].y, vs[q].y,
                          fmaf(vs[q].z, vs[q].z, vs[q].w * vs[q].w)));
        red8[q * 4 + 2] = vt[q].x + vt[q].y + vt[q].z + vt[q].w;
        red8[q * 4 + 3] = fmaf(vt[q].x, vt[q].x, fmaf(vt[q].y, vt[q].y,
                          fmaf(vt[q].z, vt[q].z, vt[q].w * vt[q].w)));
    }
    __shared__ float red[8][4];
    #pragma unroll
    for (int o = 16; o > 0; o >>= 1)
        #pragma unroll
        for (int i = 0; i < 8; ++i)
            red8[i] += __shfl_down_sync(0xffffffffu, red8[i], o);
    if (lane == 0)
        #pragma unroll
        for (int i = 0; i < 8; ++i) red[i][w] = red8[i];
    __syncthreads();

    const float invN = 1.0f / (float)HDIM;
    float muS[2], rS[2], muT[2], rT[2];
    #pragma unroll
    for (int q = 0; q < 2; ++q) {
        const float sS  = red[q*4+0][0] + red[q*4+0][1] + red[q*4+0][2] + red[q*4+0][3];
        const float ssS = red[q*4+1][0] + red[q*4+1][1] + red[q*4+1][2] + red[q*4+1][3];
        const float sT  = red[q*4+2][0] + red[q*4+2][1] + red[q*4+2][2] + red[q*4+2][3];
        const float ssT = red[q*4+3][0] + red[q*4+3][1] + red[q*4+3][2] + red[q*4+3][3];
        muS[q] = sS * invN;
        rS[q]  = rsqrtf(ssS * invN - muS[q] * muS[q] + EPSV);
        muT[q] = sT * invN;
        rT[q]  = rsqrtf(ssT * invN - muT[q] * muT[q] + EPSV);
    }

    const float4 gs = reinterpret_cast<const float4*>(g_sn)[tid];
    const float4 bs = reinterpret_cast<const float4*>(be_sn)[tid];
    const float4 gt = reinterpret_cast<const float4*>(g_tn)[tid];
    const float4 bt = reinterpret_cast<const float4*>(be_tn)[tid];

    float4 sn[2], tn[2];
    #pragma unroll
    for (int q = 0; q < 2; ++q) {
        sn[q].x = (vs[q].x - muS[q]) * rS[q] * gs.x + bs.x;
        sn[q].y = (vs[q].y - muS[q]) * rS[q] * gs.y + bs.y;
        sn[q].z = (vs[q].z - muS[q]) * rS[q] * gs.z + bs.z;
        sn[q].w = (vs[q].w - muS[q]) * rS[q] * gs.w + bs.w;
        tn[q].x = (vt[q].x - muT[q]) * rT[q] * gt.x + bt.x;
        tn[q].y = (vt[q].y - muT[q]) * rT[q] * gt.y + bt.y;
        tn[q].z = (vt[q].z - muT[q]) * rT[q] * gt.z + bt.z;
        tn[q].w = (vt[q].w - muT[q]) * rT[q] * gt.w + bt.w;
    }

    float dot[2][NTAU];
    #pragma unroll
    for (int t = 0; t < NTAU; ++t) {
        const size_t tb = (size_t)t * BDIM * HDIM >> 2;
        #pragma unroll
        for (int q = 0; q < 2; ++q) {
            const float4 sa = reinterpret_cast<const float4*>(s_att)[tb + off4[q] + tid];
            dot[q][t] = fmaf(sa.x, sn[q].x, fmaf(sa.y, sn[q].y,
                        fmaf(sa.z, sn[q].z, sa.w * sn[q].w)));
        }
    }
    __shared__ float sh[2][NTAU][4];
    #pragma unroll
    for (int q = 0; q < 2; ++q)
        #pragma unroll
        for (int t = 0; t < NTAU; ++t) {
            float d = dot[q][t];
            #pragma unroll
            for (int o = 16; o > 0; o >>= 1)
                d += __shfl_down_sync(0xffffffffu, d, o);
            if (lane == 0) sh[q][t][w] = d;
        }
    __syncthreads();

    const float scale = rsqrtf((float)HDIM);
    float wt[2][NTAU];
    #pragma unroll
    for (int q = 0; q < 2; ++q) {
        float mx = -1e30f;
        #pragma unroll
        for (int t = 0; t < NTAU; ++t) {
            float v = (sh[q][t][0] + sh[q][t][1] + sh[q][t][2] + sh[q][t][3]) * scale;
            wt[q][t] = v;
            mx = fmaxf(mx, v);
        }
        float sum = 0.f;
        #pragma unroll
        for (int t = 0; t < NTAU; ++t) { wt[q][t] = expf(wt[q][t] - mx); sum += wt[q][t]; }
        const float inv = 1.0f / sum;
        #pragma unroll
        for (int t = 0; t < NTAU; ++t) wt[q][t] *= inv;
    }

    float4 trend[2] = {{0.f,0.f,0.f,0.f}, {0.f,0.f,0.f,0.f}};
    #pragma unroll
    for (int t = 0; t < NTAU; ++t) {
        const size_t tb = (size_t)t * BDIM * HDIM >> 2;
        #pragma unroll
        for (int q = 0; q < 2; ++q) {
            const float4 ta = reinterpret_cast<const float4*>(t_att)[tb + off4[q] + tid];
            trend[q].x = fmaf(wt[q][t], ta.x, trend[q].x);
            trend[q].y = fmaf(wt[q][t], ta.y, trend[q].y);
            trend[q].z = fmaf(wt[q][t], ta.z, trend[q].z);
            trend[q].w = fmaf(wt[q][t], ta.w, trend[q].w);
        }
    }

    #pragma unroll
    for (int q = 0; q < 2; ++q) {
        const float4 tt = reinterpret_cast<const float4*>(T_t)[off4[q] + tid];
        const float g0 = sigmoidf_(tn[q].x);
        const float g1 = sigmoidf_(tn[q].y);
        const float g2 = sigmoidf_(tn[q].z);
        const float g3 = sigmoidf_(tn[q].w);
        const float o0 = tt.x * g0 + (1.0f - g0) * trend[q].x;
        const float o1 = tt.y * g1 + (1.0f - g1) * trend[q].y;
        const float o2 = tt.z * g2 + (1.0f - g2) * trend[q].z;
        const float o3 = tt.w * g3 + (1.0f - g3) * trend[q].w;
        __half2* out2 = reinterpret_cast<__half2*>(T_fusion) + off4[q] * 2 + tid * 2;
        out2[0] = __floats2half2_rn(o0, o1);
        out2[1] = __floats2half2_rn(o2, o3);
    }
}

// ---------------- fused LN(1536)x2 + split/gate/residual (fp16 inputs) ------
__global__ void __launch_bounds__(384) ln_gate_kernel(
    const __half* __restrict__ Tcat, const __half* __restrict__ Scat,
    const float* __restrict__ S_t,
    const float* __restrict__ g_t, const float* __restrict__ be_t,
    const float* __restrict__ g_s, const float* __restrict__ be_s,
    float* __restrict__ out)
{
    constexpr int N3 = 3 * HDIM;         // 1536
    const int b = blockIdx.x;
    const int tid = threadIdx.x;
    const size_t base4 = ((size_t)b * N3) >> 2;

    __shared__ float shT[N3];
    __shared__ float shS[N3];
    __shared__ float red[4][12];

    const float4 tv = ld_h4(Tcat, base4 + tid);
    const float4 sv = ld_h4(Scat, base4 + tid);

    float sT  = tv.x + tv.y + tv.z + tv.w;
    float ssT = fmaf(tv.x, tv.x, fmaf(tv.y, tv.y, fmaf(tv.z, tv.z, tv.w * tv.w)));
    float sS  = sv.x + sv.y + sv.z + sv.w;
    float ssS = fmaf(sv.x, sv.x, fmaf(sv.y, sv.y, fmaf(sv.z, sv.z, sv.w * sv.w)));

    const int lane = tid & 31, w = tid >> 5;   // 12 warps
    #pragma unroll
    for (int o = 16; o > 0; o >>= 1) {
        sT  += __shfl_down_sync(0xffffffffu, sT,  o);
        ssT += __shfl_down_sync(0xffffffffu, ssT, o);
        sS  += __shfl_down_sync(0xffffffffu, sS,  o);
        ssS += __shfl_down_sync(0xffffffffu, ssS, o);
    }
    if (lane == 0) { red[0][w] = sT; red[1][w] = ssT; red[2][w] = sS; red[3][w] = ssS; }
    __syncthreads();
    float tS = 0.f, tSS = 0.f, zS = 0.f, zSS = 0.f;
    #pragma unroll
    for (int i = 0; i < 12; ++i) {
        tS += red[0][i]; tSS += red[1][i];
        zS += red[2][i]; zSS += red[3][i];
    }
    const float invN = 1.0f / (float)N3;
    const float muT  = tS * invN;
    const float varT = tSS * invN - muT * muT;
    const float rT   = rsqrtf(varT + EPSV);
    const float muS  = zS * invN;
    const float varS = zSS * invN - muS * muS;
    const float rS   = rsqrtf(varS + EPSV);

    const float4 gt = reinterpret_cast<const float4*>(g_t)[tid];
    const float4 bt = reinterpret_cast<const float4*>(be_t)[tid];
    const float4 gs = reinterpret_cast<const float4*>(g_s)[tid];
    const float4 bs = reinterpret_cast<const float4*>(be_s)[tid];

    const int c = tid * 4;
    shT[c + 0] = (tv.x - muT) * rT * gt.x + bt.x;
    shT[c + 1] = (tv.y - muT) * rT * gt.y + bt.y;
    shT[c + 2] = (tv.z - muT) * rT * gt.z + bt.z;
    shT[c + 3] = (tv.w - muT) * rT * gt.w + bt.w;
    shS[c + 0] = (sv.x - muS) * rS * gs.x + bs.x;
    shS[c + 1] = (sv.y - muS) * rS * gs.y + bs.y;
    shS[c + 2] = (sv.z - muS) * rS * gs.z + bs.z;
    shS[c + 3] = (sv.w - muS) * rS * gs.w + bs.w;
    __syncthreads();

    for (int j = tid; j < HDIM; j += 384) {
        const float tg = sigmoidf_(shT[j]);
        const float sg = sigmoidf_(shS[j]);
        const float T_new = tg * shT[HDIM + j] + (1.0f - tg) * shS[HDIM + j];
        const float S_new = sg * shS[2 * HDIM + j] + (1.0f - sg) * shT[2 * HDIM + j]
                          + S_t[(size_t)b * HDIM + j];
        out[(size_t)b * HDIM + j] = T_new;
        out[(size_t)BDIM * HDIM + (size_t)b * HDIM + j] = S_new;
    }
}

// ---------------- launch -----------------------------------------------------
extern "C" void kernel_launch(void* const* d_in, const int* in_sizes, int n_in,
                              void* d_out, int out_size)
{
    const float* T_t   = (const float*)d_in[0];
    const float* S_t   = (const float*)d_in[1];
    const float* t_att = (const float*)d_in[2];
    const float* s_att = (const float*)d_in[3];
    const float* W_tn  = (const float*)d_in[4];
    const float* b_tn  = (const float*)d_in[5];
    const float* g_tn  = (const float*)d_in[6];
    const float* be_tn = (const float*)d_in[7];
    const float* W_sn  = (const float*)d_in[8];
    const float* b_sn  = (const float*)d_in[9];
    const float* g_sn  = (const float*)d_in[10];
    const float* be_sn = (const float*)d_in[11];
    const float* W_t   = (const float*)d_in[12];
    const float* b_t   = (const float*)d_in[13];
    const float* g_t   = (const float*)d_in[14];
    const float* be_t  = (const float*)d_in[15];
    const float* W_s   = (const float*)d_in[16];
    const float* b_s   = (const float*)d_in[17];
    const float* g_s   = (const float*)d_in[18];
    const float* be_s  = (const float*)d_in[19];
    float* out = (float*)d_out;

    __half *bufT, *bufS, *rawS, *rawT, *tfus, *Tr, *Sr;
    __half *Wtn_t, *Wsn_t, *Wt_t, *Ws_t;
    cudaGetSymbolAddress((void**)&bufT,  g_bufT);
    cudaGetSymbolAddress((void**)&bufS,  g_bufS);
    cudaGetSymbolAddress((void**)&rawS,  g_rawS);
    cudaGetSymbolAddress((void**)&rawT,  g_rawT);
    cudaGetSymbolAddress((void**)&tfus,  g_tfus);
    cudaGetSymbolAddress((void**)&Tr,    g_Tr);
    cudaGetSymbolAddress((void**)&Sr,    g_Sr);
    cudaGetSymbolAddress((void**)&Wtn_t, g_Wtn_t);
    cudaGetSymbolAddress((void**)&Wsn_t, g_Wsn_t);
    cudaGetSymbolAddress((void**)&Wt_t,  g_Wt_t);
    cudaGetSymbolAddress((void**)&Ws_t,  g_Ws_t);

    const int GEMM_SMEM = 3 * 15360;   // 46080 B (3 stages, 128x64 tile)
    cudaFuncSetAttribute(gemm_f16, cudaFuncAttributeMaxDynamicSharedMemorySize,
                         GEMM_SMEM);
    cudaFuncSetAttribute(gemm3_f16, cudaFuncAttributeMaxDynamicSharedMemorySize,
                         GEMM_SMEM);

    // ---- merged prepass (1 launch) ----
    prep_all<<<dim3(48, 16, 6), dim3(32, 32)>>>(
        W_sn, W_tn, W_t, W_s, S_t, T_t,
        Wsn_t, Wtn_t, Wt_t, Ws_t, Sr, Tr);

    // ---- 3 independent GEMMs in one flat launch (S_concat, rawS, rawT) ----
    gemm3_f16<<<5120, 256, GEMM_SMEM>>>(
        Sr, Tr, Wsn_t, Wtn_t, Ws_t, b_sn, b_tn, b_s, rawS, rawT, bufS);
    // fused LN + LN + attention + fusion gate (2 rows/block)
    ln2_attn_fusion<<<BDIM / 2, 128>>>(rawS, rawT, g_sn, be_sn, g_tn, be_tn,
                                       T_t, t_att, s_att, tfus);
    // T_concat raw (fp16)
    gemm_f16<<<dim3(24, 128), 256, GEMM_SMEM>>>(tfus, Wt_t, b_t, bufT, 3 * HDIM);
    // fused LN + LN + gate + residual -> out
    ln_gate_kernel<<<BDIM, 384>>>(bufT, bufS, S_t, g_t, be_t, g_s, be_s, out);
}

// round 16
// speedup vs baseline: 1.1404x; 1.1404x over previous
#include <cuda_runtime.h>
#include <cuda_fp16.h>
#include <math.h>
#include <stdint.h>

#define BDIM 16384
#define HDIM 512
#define NTAU 5
#define EPSV 1e-5f

// ---------------- scratch (static __device__: allocation-guard safe) --------
__device__ __half g_bufT[(size_t)BDIM * 3 * HDIM];   // fp16 raw T_concat
__device__ __half g_bufS[(size_t)BDIM * 3 * HDIM];   // fp16 raw S_concat
__device__ __half g_rawS[(size_t)BDIM * HDIM];       // fp16 raw s_next (pre-LN)
__device__ __half g_rawT[(size_t)BDIM * HDIM];       // fp16 raw t_next (pre-LN)
__device__ __half g_tfus[(size_t)BDIM * HDIM];       // fp16 T_fusion
__device__ __half g_Tr[(size_t)BDIM * HDIM];         // fp16 T_t
__device__ __half g_Sr[(size_t)BDIM * HDIM];         // fp16 S_t
__device__ __half g_Wtn_t[(size_t)HDIM * HDIM];      // transposed fp16 weights
__device__ __half g_Wsn_t[(size_t)HDIM * HDIM];
__device__ __half g_Wt_t[(size_t)3 * HDIM * HDIM];
__device__ __half g_Ws_t[(size_t)3 * HDIM * HDIM];

// ---------------- helpers ----------------------------------------------------
__device__ __forceinline__ uint32_t smem_u32(const void* p) {
    uint32_t a;
    asm("{ .reg .u64 t; cvta.to.shared.u64 t, %1; cvt.u32.u64 %0, t; }" : "=r"(a) : "l"(p));
    return a;
}
__device__ __forceinline__ float sigmoidf_(float x) {
    return 1.0f / (1.0f + __expf(-x));
}
__device__ __forceinline__ float4 ld_h4(const __half* p, size_t idx4) {
    const uint2 raw = reinterpret_cast<const uint2*>(p)[idx4];
    const float2 f01 = __half22float2(*reinterpret_cast<const __half2*>(&raw.x));
    const float2 f23 = __half22float2(*reinterpret_cast<const __half2*>(&raw.y));
    return make_float4(f01.x, f01.y, f23.x, f23.y);
}
#define CP16(s, g) asm volatile("cp.async.cg.shared.global [%0], [%1], 16;" :: "r"(s), "l"(g))
#define CP_COMMIT() asm volatile("cp.async.commit_group;" ::: "memory")
#define LDM_X4(r0, r1, r2, r3, ad) \
    asm volatile("ldmatrix.sync.aligned.m8n8.x4.shared.b16 {%0,%1,%2,%3}, [%4];" \
        : "=r"(r0), "=r"(r1), "=r"(r2), "=r"(r3) : "r"(ad))

// ---------------- merged prepass: 4 transposes + 2 fp32->fp16 converts ------
__global__ void prep_all(
    const float* __restrict__ W_sn, const float* __restrict__ W_tn,
    const float* __restrict__ W_t,  const float* __restrict__ W_s,
    const float* __restrict__ S,    const float* __restrict__ T,
    __half* __restrict__ O_sn, __half* __restrict__ O_tn,
    __half* __restrict__ O_t,  __half* __restrict__ O_s,
    __half* __restrict__ Sh,   __half* __restrict__ Th)
{
    const int z = blockIdx.z;
    if (z >= 4) {
        const float* in = (z == 4) ? S : T;
        __half* out     = (z == 4) ? Sh : Th;
        const int th = (blockIdx.y * 48 + blockIdx.x) * 1024 +
                       threadIdx.y * 32 + threadIdx.x;     // 0..786431
        constexpr int TOT4 = BDIM * HDIM / 4;              // 2097152
        #pragma unroll
        for (int i = 0; i < 3; ++i) {
            const int idx = th + i * 786432;
            if (idx < TOT4) {
                float4 v = reinterpret_cast<const float4*>(in)[idx];
                __half2* o2 = reinterpret_cast<__half2*>(out) + (size_t)idx * 2;
                o2[0] = __floats2half2_rn(v.x, v.y);
                o2[1] = __floats2half2_rn(v.z, v.w);
            }
        }
        return;
    }
    const float* W; __half* O; int N;
    if      (z == 0) { W = W_sn; O = O_sn; N = HDIM; }
    else if (z == 1) { W = W_tn; O = O_tn; N = HDIM; }
    else if (z == 2) { W = W_t;  O = O_t;  N = 3 * HDIM; }
    else             { W = W_s;  O = O_s;  N = 3 * HDIM; }
    if (blockIdx.x * 32 >= N) return;

    __shared__ float tile[32][33];
    const int x = blockIdx.x * 32 + threadIdx.x;   // n
    const int y = blockIdx.y * 32 + threadIdx.y;   // k
    tile[threadIdx.y][threadIdx.x] = W[(size_t)y * N + x];
    __syncthreads();
    const int xo = blockIdx.y * 32 + threadIdx.x;  // k
    const int yo = blockIdx.x * 32 + threadIdx.y;  // n
    O[(size_t)yo * HDIM + xo] = __float2half_rn(tile[threadIdx.x][threadIdx.y]);
}

// ---------------- fp16 mma.sync GEMM body (R14-exact) ------------------------
// 128x128 CTA tile, BK=32, 3-stage cp.async, warp tile 64x32 (m16n8k16).
__device__ __forceinline__ void gemm_body(
    const __half* __restrict__ A, const __half* __restrict__ Bt,
    const float* __restrict__ bias, __half* __restrict__ C, int N,
    int bx, int by, char* smem)
{
    constexpr int K = 512, BK = 32, NT = K / BK;   // 16 k-iters
    constexpr int LDB = 80;                        // bytes per row (32h + 8h pad)
    constexpr int TILEB = 128 * LDB;               // 10240 B per operand tile
    constexpr int STAGEB = 2 * TILEB;              // 20480 B per stage
    const uint32_t sb = smem_u32(smem);

    const int tid  = threadIdx.x;
    const int wid  = tid >> 5;
    const int lane = tid & 31;
    const int wm   = wid & 1;
    const int wn   = wid >> 1;
    const int m0 = by * 128;
    const int n0 = bx * 128;

    const int r  = tid >> 1;
    const int ch = tid & 1;
    const __half* Ag = A  + (size_t)(m0 + r) * K + ch * 16;
    const __half* Bg = Bt + (size_t)(n0 + r) * K + ch * 16;
    const uint32_t srow = (uint32_t)(r * LDB + ch * 32);

    auto load = [&](int kt) {
        const uint32_t sa = sb + (uint32_t)((kt % 3) * STAGEB) + srow;
        const uint32_t sbb = sa + TILEB;
        const __half* ag = Ag + kt * BK;
        const __half* bg = Bg + kt * BK;
        CP16(sa,      ag);
        CP16(sa + 16, ag + 8);
        CP16(sbb,      bg);
        CP16(sbb + 16, bg + 8);
        CP_COMMIT();
    };

    load(0);
    load(1);

    float acc[4][4][4];
    #pragma unroll
    for (int i = 0; i < 4; ++i)
        #pragma unroll
        for (int j = 0; j < 4; ++j)
            #pragma unroll
            for (int q = 0; q < 4; ++q) acc[i][j][q] = 0.f;

    const int r8 = lane & 7;
    const int g  = lane >> 3;
    const int ga = g & 1;
    const int gb = g >> 1;

    for (int kt = 0; kt < NT; ++kt) {
        if (kt < NT - 1) asm volatile("cp.async.wait_group 1;" ::: "memory");
        else             asm volatile("cp.async.wait_group 0;" ::: "memory");
        __syncthreads();
        if (kt + 2 < NT) load(kt + 2);

        const uint32_t st = sb + (uint32_t)((kt % 3) * STAGEB);

        #pragma unroll
        for (int ks = 0; ks < 2; ++ks) {
            uint32_t af[4][4];
            #pragma unroll
            for (int mi = 0; mi < 4; ++mi) {
                const uint32_t ad = st +
                    (uint32_t)((wm * 64 + mi * 16 + ga * 8 + r8) * LDB +
                               (ks * 16 + gb * 8) * 2);
                LDM_X4(af[mi][0], af[mi][1], af[mi][2], af[mi][3], ad);
            }
            uint32_t bfr[2][4];
            #pragma unroll
            for (int p = 0; p < 2; ++p) {
                const uint32_t bd = st + TILEB +
                    (uint32_t)((wn * 32 + p * 16 + gb * 8 + r8) * LDB +
                               (ks * 16 + ga * 8) * 2);
                LDM_X4(bfr[p][0], bfr[p][1], bfr[p][2], bfr[p][3], bd);
            }
            #pragma unroll
            for (int mi = 0; mi < 4; ++mi)
                #pragma unroll
                for (int ni = 0; ni < 4; ++ni) {
                    float* d = acc[mi][ni];
                    const uint32_t b0 = bfr[ni >> 1][(ni & 1) * 2];
                    const uint32_t b1 = bfr[ni >> 1][(ni & 1) * 2 + 1];
                    asm volatile(
                        "mma.sync.aligned.m16n8k16.row.col.f32.f16.f16.f32 "
                        "{%0,%1,%2,%3}, {%4,%5,%6,%7}, {%8,%9}, {%0,%1,%2,%3};"
                        : "+f"(d[0]), "+f"(d[1]), "+f"(d[2]), "+f"(d[3])
                        : "r"(af[mi][0]), "r"(af[mi][1]), "r"(af[mi][2]), "r"(af[mi][3]),
                          "r"(b0), "r"(b1));
                }
        }
    }

    const int gm   = lane >> 2;
    const int colq = (lane & 3) * 2;
    #pragma unroll
    for (int ni = 0; ni < 4; ++ni) {
        const int col = n0 + wn * 32 + ni * 8 + colq;
        const float b0 = bias[col], b1 = bias[col + 1];
        #pragma unroll
        for (int mi = 0; mi < 4; ++mi) {
            const int row = m0 + wm * 64 + mi * 16 + gm;
            *reinterpret_cast<__half2*>(C + (size_t)row * N + col) =
                __floats2half2_rn(acc[mi][ni][0] + b0, acc[mi][ni][1] + b1);
            *reinterpret_cast<__half2*>(C + (size_t)(row + 8) * N + col) =
                __floats2half2_rn(acc[mi][ni][2] + b0, acc[mi][ni][3] + b1);
        }
    }
}

// Single-GEMM launcher (T_concat)
__global__ void __launch_bounds__(256, 2) gemm_f16(
    const __half* __restrict__ A, const __half* __restrict__ Bt,
    const float* __restrict__ bias, __half* __restrict__ C, int N)
{
    extern __shared__ char smem[];
    gemm_body(A, Bt, bias, C, N, blockIdx.x, blockIdx.y, smem);
}

// Fused launcher: 2560 CTAs flat. [0,1536) S_concat, [1536,2048) rawS,
// [2048,2560) rawT.
__global__ void __launch_bounds__(256, 2) gemm3_f16(
    const __half* __restrict__ Sr, const __half* __restrict__ Tr,
    const __half* __restrict__ Wsn, const __half* __restrict__ Wtn,
    const __half* __restrict__ Ws,
    const float* __restrict__ b_sn, const float* __restrict__ b_tn,
    const float* __restrict__ b_s,
    __half* __restrict__ rawS, __half* __restrict__ rawT,
    __half* __restrict__ bufS)
{
    extern __shared__ char smem[];
    const int id = blockIdx.x;
    if (id < 1536) {
        gemm_body(Sr, Ws, b_s, bufS, 3 * HDIM, id % 12, id / 12, smem);
    } else if (id < 2048) {
        const int l = id - 1536;
        gemm_body(Sr, Wsn, b_sn, rawS, HDIM, l & 3, l >> 2, smem);
    } else {
        const int l = id - 2048;
        gemm_body(Tr, Wtn, b_tn, rawT, HDIM, l & 3, l >> 2, smem);
    }
}

// ---------------- fused LN+LN+attention+gate, TWO rows per 128-thr block ----
__global__ void __launch_bounds__(128) ln2_attn_fusion(
    const __half* __restrict__ rawS, const __half* __restrict__ rawT,
    const float* __restrict__ g_sn, const float* __restrict__ be_sn,
    const float* __restrict__ g_tn, const float* __restrict__ be_tn,
    const float* __restrict__ T_t,  const float* __restrict__ t_att,
    const float* __restrict__ s_att, __half* __restrict__ T_fusion)
{
    const int tid = threadIdx.x;
    const int lane = tid & 31, w = tid >> 5;
    size_t off4[2];
    off4[0] = ((size_t)(blockIdx.x * 2) * HDIM) >> 2;
    off4[1] = off4[0] + (HDIM >> 2);

    float4 vs[2], vt[2];
    #pragma unroll
    for (int q = 0; q < 2; ++q) {
        vs[q] = ld_h4(rawS, off4[q] + tid);
        vt[q] = ld_h4(rawT, off4[q] + tid);
    }

    float red8[8];
    #pragma unroll
    for (int q = 0; q < 2; ++q) {
        red8[q * 4 + 0] = vs[q].x + vs[q].y + vs[q].z + vs[q].w;
        red8[q * 4 + 1] = fmaf(vs[q].x, vs[q].x, fmaf(vs[q].y, vs[q].y,
                          fmaf(vs[q].z, vs[q].z, vs[q].w * vs[q].w)));
        red8[q * 4 + 2] = vt[q].x + vt[q].y + vt[q].z + vt[q].w;
        red8[q * 4 + 3] = fmaf(vt[q].x, vt[q].x, fmaf(vt[q].y, vt[q].y,
                          fmaf(vt[q].z, vt[q].z, vt[q].w * vt[q].w)));
    }
    __shared__ float red[8][4];
    #pragma unroll
    for (int o = 16; o > 0; o >>= 1)
        #pragma unroll
        for (int i = 0; i < 8; ++i)
            red8[i] += __shfl_down_sync(0xffffffffu, red8[i], o);
    if (lane == 0)
        #pragma unroll
        for (int i = 0; i < 8; ++i) red[i][w] = red8[i];
    __syncthreads();

    const float invN = 1.0f / (float)HDIM;
    float muS[2], rS[2], muT[2], rT[2];
    #pragma unroll
    for (int q = 0; q < 2; ++q) {
        const float sS  = red[q*4+0][0] + red[q*4+0][1] + red[q*4+0][2] + red[q*4+0][3];
        const float ssS = red[q*4+1][0] + red[q*4+1][1] + red[q*4+1][2] + red[q*4+1][3];
        const float sT  = red[q*4+2][0] + red[q*4+2][1] + red[q*4+2][2] + red[q*4+2][3];
        const float ssT = red[q*4+3][0] + red[q*4+3][1] + red[q*4+3][2] + red[q*4+3][3];
        muS[q] = sS * invN;
        rS[q]  = rsqrtf(ssS * invN - muS[q] * muS[q] + EPSV);
        muT[q] = sT * invN;
        rT[q]  = rsqrtf(ssT * invN - muT[q] * muT[q] + EPSV);
    }

    const float4 gs = reinterpret_cast<const float4*>(g_sn)[tid];
    const float4 bs = reinterpret_cast<const float4*>(be_sn)[tid];
    const float4 gt = reinterpret_cast<const float4*>(g_tn)[tid];
    const float4 bt = reinterpret_cast<const float4*>(be_tn)[tid];

    float4 sn[2], tn[2];
    #pragma unroll
    for (int q = 0; q < 2; ++q) {
        sn[q].x = (vs[q].x - muS[q]) * rS[q] * gs.x + bs.x;
        sn[q].y = (vs[q].y - muS[q]) * rS[q] * gs.y + bs.y;
        sn[q].z = (vs[q].z - muS[q]) * rS[q] * gs.z + bs.z;
        sn[q].w = (vs[q].w - muS[q]) * rS[q] * gs.w + bs.w;
        tn[q].x = (vt[q].x - muT[q]) * rT[q] * gt.x + bt.x;
        tn[q].y = (vt[q].y - muT[q]) * rT[q] * gt.y + bt.y;
        tn[q].z = (vt[q].z - muT[q]) * rT[q] * gt.z + bt.z;
        tn[q].w = (vt[q].w - muT[q]) * rT[q] * gt.w + bt.w;
    }

    float dot[2][NTAU];
    #pragma unroll
    for (int t = 0; t < NTAU; ++t) {
        const size_t tb = (size_t)t * BDIM * HDIM >> 2;
        #pragma unroll
        for (int q = 0; q < 2; ++q) {
            const float4 sa = reinterpret_cast<const float4*>(s_att)[tb + off4[q] + tid];
            dot[q][t] = fmaf(sa.x, sn[q].x, fmaf(sa.y, sn[q].y,
                        fmaf(sa.z, sn[q].z, sa.w * sn[q].w)));
        }
    }
    __shared__ float sh[2][NTAU][4];
    #pragma unroll
    for (int q = 0; q < 2; ++q)
        #pragma unroll
        for (int t = 0; t < NTAU; ++t) {
            float d = dot[q][t];
            #pragma unroll
            for (int o = 16; o > 0; o >>= 1)
                d += __shfl_down_sync(0xffffffffu, d, o);
            if (lane == 0) sh[q][t][w] = d;
        }
    __syncthreads();

    const float scale = rsqrtf((float)HDIM);
    float wt[2][NTAU];
    #pragma unroll
    for (int q = 0; q < 2; ++q) {
        float mx = -1e30f;
        #pragma unroll
        for (int t = 0; t < NTAU; ++t) {
            float v = (sh[q][t][0] + sh[q][t][1] + sh[q][t][2] + sh[q][t][3]) * scale;
            wt[q][t] = v;
            mx = fmaxf(mx, v);
        }
        float sum = 0.f;
        #pragma unroll
        for (int t = 0; t < NTAU; ++t) { wt[q][t] = expf(wt[q][t] - mx); sum += wt[q][t]; }
        const float inv = 1.0f / sum;
        #pragma unroll
        for (int t = 0; t < NTAU; ++t) wt[q][t] *= inv;
    }

    float4 trend[2] = {{0.f,0.f,0.f,0.f}, {0.f,0.f,0.f,0.f}};
    #pragma unroll
    for (int t = 0; t < NTAU; ++t) {
        const size_t tb = (size_t)t * BDIM * HDIM >> 2;
        #pragma unroll
        for (int q = 0; q < 2; ++q) {
            const float4 ta = reinterpret_cast<const float4*>(t_att)[tb + off4[q] + tid];
            trend[q].x = fmaf(wt[q][t], ta.x, trend[q].x);
            trend[q].y = fmaf(wt[q][t], ta.y, trend[q].y);
            trend[q].z = fmaf(wt[q][t], ta.z, trend[q].z);
            trend[q].w = fmaf(wt[q][t], ta.w, trend[q].w);
        }
    }

    #pragma unroll
    for (int q = 0; q < 2; ++q) {
        const float4 tt = reinterpret_cast<const float4*>(T_t)[off4[q] + tid];
        const float g0 = sigmoidf_(tn[q].x);
        const float g1 = sigmoidf_(tn[q].y);
        const float g2 = sigmoidf_(tn[q].z);
        const float g3 = sigmoidf_(tn[q].w);
        const float o0 = tt.x * g0 + (1.0f - g0) * trend[q].x;
        const float o1 = tt.y * g1 + (1.0f - g1) * trend[q].y;
        const float o2 = tt.z * g2 + (1.0f - g2) * trend[q].z;
        const float o3 = tt.w * g3 + (1.0f - g3) * trend[q].w;
        __half2* out2 = reinterpret_cast<__half2*>(T_fusion) + off4[q] * 2 + tid * 2;
        out2[0] = __floats2half2_rn(o0, o1);
        out2[1] = __floats2half2_rn(o2, o3);
    }
}

// ---------------- fused LN(1536)x2 + gate/residual, TWO rows per block ------
__global__ void __launch_bounds__(384) ln_gate_kernel(
    const __half* __restrict__ Tcat, const __half* __restrict__ Scat,
    const float* __restrict__ S_t,
    const float* __restrict__ g_t, const float* __restrict__ be_t,
    const float* __restrict__ g_s, const float* __restrict__ be_s,
    float* __restrict__ out)
{
    constexpr int N3 = 3 * HDIM;         // 1536
    const int tid = threadIdx.x;
    const int lane = tid & 31, w = tid >> 5;   // 12 warps
    const int b0 = blockIdx.x * 2;

    __shared__ float shT[2][N3];
    __shared__ float shS[2][N3];
    __shared__ float red[8][12];

    float4 tv[2], sv[2];
    #pragma unroll
    for (int q = 0; q < 2; ++q) {
        const size_t base4 = ((size_t)(b0 + q) * N3) >> 2;
        tv[q] = ld_h4(Tcat, base4 + tid);
        sv[q] = ld_h4(Scat, base4 + tid);
    }

    float red8[8];
    #pragma unroll
    for (int q = 0; q < 2; ++q) {
        red8[q * 4 + 0] = tv[q].x + tv[q].y + tv[q].z + tv[q].w;
        red8[q * 4 + 1] = fmaf(tv[q].x, tv[q].x, fmaf(tv[q].y, tv[q].y,
                          fmaf(tv[q].z, tv[q].z, tv[q].w * tv[q].w)));
        red8[q * 4 + 2] = sv[q].x + sv[q].y + sv[q].z + sv[q].w;
        red8[q * 4 + 3] = fmaf(sv[q].x, sv[q].x, fmaf(sv[q].y, sv[q].y,
                          fmaf(sv[q].z, sv[q].z, sv[q].w * sv[q].w)));
    }
    #pragma unroll
    for (int o = 16; o > 0; o >>= 1)
        #pragma unroll
        for (int i = 0; i < 8; ++i)
            red8[i] += __shfl_down_sync(0xffffffffu, red8[i], o);
    if (lane == 0)
        #pragma unroll
        for (int i = 0; i < 8; ++i) red[i][w] = red8[i];
    __syncthreads();

    const float invN = 1.0f / (float)N3;
    float muT[2], rT[2], muS[2], rS[2];
    #pragma unroll
    for (int q = 0; q < 2; ++q) {
        float tS = 0.f, tSS = 0.f, zS = 0.f, zSS = 0.f;
        #pragma unroll
        for (int i = 0; i < 12; ++i) {
            tS += red[q*4+0][i]; tSS += red[q*4+1][i];
            zS += red[q*4+2][i]; zSS += red[q*4+3][i];
        }
        muT[q] = tS * invN;
        rT[q]  = rsqrtf(tSS * invN - muT[q] * muT[q] + EPSV);
        muS[q] = zS * invN;
        rS[q]  = rsqrtf(zSS * invN - muS[q] * muS[q] + EPSV);
    }

    const float4 gt = reinterpret_cast<const float4*>(g_t)[tid];
    const float4 bt = reinterpret_cast<const float4*>(be_t)[tid];
    const float4 gs = reinterpret_cast<const float4*>(g_s)[tid];
    const float4 bs = reinterpret_cast<const float4*>(be_s)[tid];

    const int c = tid * 4;
    #pragma unroll
    for (int q = 0; q < 2; ++q) {
        shT[q][c + 0] = (tv[q].x - muT[q]) * rT[q] * gt.x + bt.x;
        shT[q][c + 1] = (tv[q].y - muT[q]) * rT[q] * gt.y + bt.y;
        shT[q][c + 2] = (tv[q].z - muT[q]) * rT[q] * gt.z + bt.z;
        shT[q][c + 3] = (tv[q].w - muT[q]) * rT[q] * gt.w + bt.w;
        shS[q][c + 0] = (sv[q].x - muS[q]) * rS[q] * gs.x + bs.x;
        shS[q][c + 1] = (sv[q].y - muS[q]) * rS[q] * gs.y + bs.y;
        shS[q][c + 2] = (sv[q].z - muS[q]) * rS[q] * gs.z + bs.z;
        shS[q][c + 3] = (sv[q].w - muS[q]) * rS[q] * gs.w + bs.w;
    }
    __syncthreads();

    #pragma unroll
    for (int q = 0; q < 2; ++q) {
        const size_t rowoff = (size_t)(b0 + q) * HDIM;
        for (int j = tid; j < HDIM; j += 384) {
            const float tg = sigmoidf_(shT[q][j]);
            const float sg = sigmoidf_(shS[q][j]);
            const float T_new = tg * shT[q][HDIM + j] + (1.0f - tg) * shS[q][HDIM + j];
            const float S_new = sg * shS[q][2 * HDIM + j] + (1.0f - sg) * shT[q][2 * HDIM + j]
                              + S_t[rowoff + j];
            out[rowoff + j] = T_new;
            out[(size_t)BDIM * HDIM + rowoff + j] = S_new;
        }
    }
}

// ---------------- launch -----------------------------------------------------
extern "C" void kernel_launch(void* const* d_in, const int* in_sizes, int n_in,
                              void* d_out, int out_size)
{
    const float* T_t   = (const float*)d_in[0];
    const float* S_t   = (const float*)d_in[1];
    const float* t_att = (const float*)d_in[2];
    const float* s_att = (const float*)d_in[3];
    const float* W_tn  = (const float*)d_in[4];
    const float* b_tn  = (const float*)d_in[5];
    const float* g_tn  = (const float*)d_in[6];
    const float* be_tn = (const float*)d_in[7];
    const float* W_sn  = (const float*)d_in[8];
    const float* b_sn  = (const float*)d_in[9];
    const float* g_sn  = (const float*)d_in[10];
    const float* be_sn = (const float*)d_in[11];
    const float* W_t   = (const float*)d_in[12];
    const float* b_t   = (const float*)d_in[13];
    const float* g_t   = (const float*)d_in[14];
    const float* be_t  = (const float*)d_in[15];
    const float* W_s   = (const float*)d_in[16];
    const float* b_s   = (const float*)d_in[17];
    const float* g_s   = (const float*)d_in[18];
    const float* be_s  = (const float*)d_in[19];
    float* out = (float*)d_out;

    __half *bufT, *bufS, *rawS, *rawT, *tfus, *Tr, *Sr;
    __half *Wtn_t, *Wsn_t, *Wt_t, *Ws_t;
    cudaGetSymbolAddress((void**)&bufT,  g_bufT);
    cudaGetSymbolAddress((void**)&bufS,  g_bufS);
    cudaGetSymbolAddress((void**)&rawS,  g_rawS);
    cudaGetSymbolAddress((void**)&rawT,  g_rawT);
    cudaGetSymbolAddress((void**)&tfus,  g_tfus);
    cudaGetSymbolAddress((void**)&Tr,    g_Tr);
    cudaGetSymbolAddress((void**)&Sr,    g_Sr);
    cudaGetSymbolAddress((void**)&Wtn_t, g_Wtn_t);
    cudaGetSymbolAddress((void**)&Wsn_t, g_Wsn_t);
    cudaGetSymbolAddress((void**)&Wt_t,  g_Wt_t);
    cudaGetSymbolAddress((void**)&Ws_t,  g_Ws_t);

    const int GEMM_SMEM = 3 * 20480;   // 61440 B (3 stages, BK=32)
    cudaFuncSetAttribute(gemm_f16, cudaFuncAttributeMaxDynamicSharedMemorySize,
                         GEMM_SMEM);
    cudaFuncSetAttribute(gemm3_f16, cudaFuncAttributeMaxDynamicSharedMemorySize,
                         GEMM_SMEM);

    // ---- merged prepass (1 launch) ----
    prep_all<<<dim3(48, 16, 6), dim3(32, 32)>>>(
        W_sn, W_tn, W_t, W_s, S_t, T_t,
        Wsn_t, Wtn_t, Wt_t, Ws_t, Sr, Tr);

    // ---- 3 independent GEMMs in one flat launch (S_concat, rawS, rawT) ----
    gemm3_f16<<<2560, 256, GEMM_SMEM>>>(
        Sr, Tr, Wsn_t, Wtn_t, Ws_t, b_sn, b_tn, b_s, rawS, rawT, bufS);
    // fused LN + LN + attention + fusion gate (2 rows/block)
    ln2_attn_fusion<<<BDIM / 2, 128>>>(rawS, rawT, g_sn, be_sn, g_tn, be_tn,
                                       T_t, t_att, s_att, tfus);
    // T_concat raw (fp16)
    gemm_f16<<<dim3(12, 128), 256, GEMM_SMEM>>>(tfus, Wt_t, b_t, bufT, 3 * HDIM);
    // fused LN + LN + gate + residual -> out (2 rows/block)
    ln_gate_kernel<<<BDIM / 2, 384>>>(bufT, bufS, S_t, g_t, be_t, g_s, be_s, out);
}

// round 17
// speedup vs baseline: 1.1538x; 1.0118x over previous
#include <cuda_runtime.h>
#include <cuda_fp16.h>
#include <math.h>
#include <stdint.h>

#define BDIM 16384
#define HDIM 512
#define NTAU 5
#define EPSV 1e-5f

// ---------------- scratch (static __device__: allocation-guard safe) --------
__device__ __half g_bufT[(size_t)BDIM * 3 * HDIM];   // fp16 raw T_concat
__device__ __half g_bufS[(size_t)BDIM * 3 * HDIM];   // fp16 raw S_concat
__device__ __half g_rawS[(size_t)BDIM * HDIM];       // fp16 raw s_next (pre-LN)
__device__ __half g_rawT[(size_t)BDIM * HDIM];       // fp16 raw t_next (pre-LN)
__device__ __half g_tfus[(size_t)BDIM * HDIM];       // fp16 T_fusion
__device__ __half g_Tr[(size_t)BDIM * HDIM];         // fp16 T_t
__device__ __half g_Sr[(size_t)BDIM * HDIM];         // fp16 S_t
__device__ __half g_Wtn_t[(size_t)HDIM * HDIM];      // transposed fp16 weights
__device__ __half g_Wsn_t[(size_t)HDIM * HDIM];
__device__ __half g_Wt_t[(size_t)3 * HDIM * HDIM];
__device__ __half g_Ws_t[(size_t)3 * HDIM * HDIM];

// ---------------- helpers ----------------------------------------------------
__device__ __forceinline__ uint32_t smem_u32(const void* p) {
    uint32_t a;
    asm("{ .reg .u64 t; cvta.to.shared.u64 t, %1; cvt.u32.u64 %0, t; }" : "=r"(a) : "l"(p));
    return a;
}
__device__ __forceinline__ float sigmoidf_(float x) {
    return 1.0f / (1.0f + __expf(-x));
}
__device__ __forceinline__ float4 ld_h4(const __half* p, size_t idx4) {
    const uint2 raw = reinterpret_cast<const uint2*>(p)[idx4];
    const float2 f01 = __half22float2(*reinterpret_cast<const __half2*>(&raw.x));
    const float2 f23 = __half22float2(*reinterpret_cast<const __half2*>(&raw.y));
    return make_float4(f01.x, f01.y, f23.x, f23.y);
}
__device__ __forceinline__ void grid_dep_wait() {
    asm volatile("griddepcontrol.wait;" ::: "memory");
}
#define CP16(s, g) asm volatile("cp.async.cg.shared.global [%0], [%1], 16;" :: "r"(s), "l"(g))
#define CP_COMMIT() asm volatile("cp.async.commit_group;" ::: "memory")
#define CP_WAIT0() asm volatile("cp.async.wait_group 0;" ::: "memory")
#define LDM_X4(r0, r1, r2, r3, ad) \
    asm volatile("ldmatrix.sync.aligned.m8n8.x4.shared.b16 {%0,%1,%2,%3}, [%4];" \
        : "=r"(r0), "=r"(r1), "=r"(r2), "=r"(r3) : "r"(ad))

// ---------------- merged prepass: 4 transposes + 2 fp32->fp16 converts ------
__global__ void prep_all(
    const float* __restrict__ W_sn, const float* __restrict__ W_tn,
    const float* __restrict__ W_t,  const float* __restrict__ W_s,
    const float* __restrict__ S,    const float* __restrict__ T,
    __half* __restrict__ O_sn, __half* __restrict__ O_tn,
    __half* __restrict__ O_t,  __half* __restrict__ O_s,
    __half* __restrict__ Sh,   __half* __restrict__ Th)
{
    const int z = blockIdx.z;
    if (z >= 4) {
        const float* in = (z == 4) ? S : T;
        __half* out     = (z == 4) ? Sh : Th;
        const int th = (blockIdx.y * 48 + blockIdx.x) * 1024 +
                       threadIdx.y * 32 + threadIdx.x;     // 0..786431
        constexpr int TOT4 = BDIM * HDIM / 4;              // 2097152
        #pragma unroll
        for (int i = 0; i < 3; ++i) {
            const int idx = th + i * 786432;
            if (idx < TOT4) {
                float4 v = reinterpret_cast<const float4*>(in)[idx];
                __half2* o2 = reinterpret_cast<__half2*>(out) + (size_t)idx * 2;
                o2[0] = __floats2half2_rn(v.x, v.y);
                o2[1] = __floats2half2_rn(v.z, v.w);
            }
        }
        return;
    }
    const float* W; __half* O; int N;
    if      (z == 0) { W = W_sn; O = O_sn; N = HDIM; }
    else if (z == 1) { W = W_tn; O = O_tn; N = HDIM; }
    else if (z == 2) { W = W_t;  O = O_t;  N = 3 * HDIM; }
    else             { W = W_s;  O = O_s;  N = 3 * HDIM; }
    if (blockIdx.x * 32 >= N) return;

    __shared__ float tile[32][33];
    const int x = blockIdx.x * 32 + threadIdx.x;   // n
    const int y = blockIdx.y * 32 + threadIdx.y;   // k
    tile[threadIdx.y][threadIdx.x] = W[(size_t)y * N + x];
    __syncthreads();
    const int xo = blockIdx.y * 32 + threadIdx.x;  // k
    const int yo = blockIdx.x * 32 + threadIdx.y;  // n
    O[(size_t)yo * HDIM + xo] = __float2half_rn(tile[threadIdx.x][threadIdx.y]);
}

// ---------------- fp16 mma.sync GEMM body (R14-exact) ------------------------
// 128x128 CTA tile, BK=32, 3-stage cp.async, warp tile 64x32 (m16n8k16).
__device__ __forceinline__ void gemm_body(
    const __half* __restrict__ A, const __half* __restrict__ Bt,
    const float* __restrict__ bias, __half* __restrict__ C, int N,
    int bx, int by, char* smem)
{
    constexpr int K = 512, BK = 32, NT = K / BK;   // 16 k-iters
    constexpr int LDB = 80;                        // bytes per row (32h + 8h pad)
    constexpr int TILEB = 128 * LDB;               // 10240 B per operand tile
    constexpr int STAGEB = 2 * TILEB;              // 20480 B per stage
    const uint32_t sb = smem_u32(smem);

    const int tid  = threadIdx.x;
    const int wid  = tid >> 5;
    const int lane = tid & 31;
    const int wm   = wid & 1;
    const int wn   = wid >> 1;
    const int m0 = by * 128;
    const int n0 = bx * 128;

    const int r  = tid >> 1;
    const int ch = tid & 1;
    const __half* Ag = A  + (size_t)(m0 + r) * K + ch * 16;
    const __half* Bg = Bt + (size_t)(n0 + r) * K + ch * 16;
    const uint32_t srow = (uint32_t)(r * LDB + ch * 32);

    auto load = [&](int kt) {
        const uint32_t sa = sb + (uint32_t)((kt % 3) * STAGEB) + srow;
        const uint32_t sbb = sa + TILEB;
        const __half* ag = Ag + kt * BK;
        const __half* bg = Bg + kt * BK;
        CP16(sa,      ag);
        CP16(sa + 16, ag + 8);
        CP16(sbb,      bg);
        CP16(sbb + 16, bg + 8);
        CP_COMMIT();
    };

    load(0);
    load(1);

    float acc[4][4][4];
    #pragma unroll
    for (int i = 0; i < 4; ++i)
        #pragma unroll
        for (int j = 0; j < 4; ++j)
            #pragma unroll
            for (int q = 0; q < 4; ++q) acc[i][j][q] = 0.f;

    const int r8 = lane & 7;
    const int g  = lane >> 3;
    const int ga = g & 1;
    const int gb = g >> 1;

    for (int kt = 0; kt < NT; ++kt) {
        if (kt < NT - 1) asm volatile("cp.async.wait_group 1;" ::: "memory");
        else             asm volatile("cp.async.wait_group 0;" ::: "memory");
        __syncthreads();
        if (kt + 2 < NT) load(kt + 2);

        const uint32_t st = sb + (uint32_t)((kt % 3) * STAGEB);

        #pragma unroll
        for (int ks = 0; ks < 2; ++ks) {
            uint32_t af[4][4];
            #pragma unroll
            for (int mi = 0; mi < 4; ++mi) {
                const uint32_t ad = st +
                    (uint32_t)((wm * 64 + mi * 16 + ga * 8 + r8) * LDB +
                               (ks * 16 + gb * 8) * 2);
                LDM_X4(af[mi][0], af[mi][1], af[mi][2], af[mi][3], ad);
            }
            uint32_t bfr[2][4];
            #pragma unroll
            for (int p = 0; p < 2; ++p) {
                const uint32_t bd = st + TILEB +
                    (uint32_t)((wn * 32 + p * 16 + gb * 8 + r8) * LDB +
                               (ks * 16 + ga * 8) * 2);
                LDM_X4(bfr[p][0], bfr[p][1], bfr[p][2], bfr[p][3], bd);
            }
            #pragma unroll
            for (int mi = 0; mi < 4; ++mi)
                #pragma unroll
                for (int ni = 0; ni < 4; ++ni) {
                    float* d = acc[mi][ni];
                    const uint32_t b0 = bfr[ni >> 1][(ni & 1) * 2];
                    const uint32_t b1 = bfr[ni >> 1][(ni & 1) * 2 + 1];
                    asm volatile(
                        "mma.sync.aligned.m16n8k16.row.col.f32.f16.f16.f32 "
                        "{%0,%1,%2,%3}, {%4,%5,%6,%7}, {%8,%9}, {%0,%1,%2,%3};"
                        : "+f"(d[0]), "+f"(d[1]), "+f"(d[2]), "+f"(d[3])
                        : "r"(af[mi][0]), "r"(af[mi][1]), "r"(af[mi][2]), "r"(af[mi][3]),
                          "r"(b0), "r"(b1));
                }
        }
    }

    const int gm   = lane >> 2;
    const int colq = (lane & 3) * 2;
    #pragma unroll
    for (int ni = 0; ni < 4; ++ni) {
        const int col = n0 + wn * 32 + ni * 8 + colq;
        const float b0 = bias[col], b1 = bias[col + 1];
        #pragma unroll
        for (int mi = 0; mi < 4; ++mi) {
            const int row = m0 + wm * 64 + mi * 16 + gm;
            *reinterpret_cast<__half2*>(C + (size_t)row * N + col) =
                __floats2half2_rn(acc[mi][ni][0] + b0, acc[mi][ni][1] + b1);
            *reinterpret_cast<__half2*>(C + (size_t)(row + 8) * N + col) =
                __floats2half2_rn(acc[mi][ni][2] + b0, acc[mi][ni][3] + b1);
        }
    }
}

// Single-GEMM launcher (T_concat)
__global__ void __launch_bounds__(256, 2) gemm_f16(
    const __half* __restrict__ A, const __half* __restrict__ Bt,
    const float* __restrict__ bias, __half* __restrict__ C, int N)
{
    extern __shared__ char smem[];
    gemm_body(A, Bt, bias, C, N, blockIdx.x, blockIdx.y, smem);
}

// Fused launcher: 2560 CTAs flat. [0,1536) S_concat, [1536,2048) rawS,
// [2048,2560) rawT.
__global__ void __launch_bounds__(256, 2) gemm3_f16(
    const __half* __restrict__ Sr, const __half* __restrict__ Tr,
    const __half* __restrict__ Wsn, const __half* __restrict__ Wtn,
    const __half* __restrict__ Ws,
    const float* __restrict__ b_sn, const float* __restrict__ b_tn,
    const float* __restrict__ b_s,
    __half* __restrict__ rawS, __half* __restrict__ rawT,
    __half* __restrict__ bufS)
{
    extern __shared__ char smem[];
    const int id = blockIdx.x;
    if (id < 1536) {
        gemm_body(Sr, Ws, b_s, bufS, 3 * HDIM, id % 12, id / 12, smem);
    } else if (id < 2048) {
        const int l = id - 1536;
        gemm_body(Sr, Wsn, b_sn, rawS, HDIM, l & 3, l >> 2, smem);
    } else {
        const int l = id - 2048;
        gemm_body(Tr, Wtn, b_tn, rawT, HDIM, l & 3, l >> 2, smem);
    }
}

// ---------------- fused LN+LN+attention+gate, 2 rows/block, PDL prefetch ----
__global__ void __launch_bounds__(128) ln2_attn_fusion(
    const __half* __restrict__ rawS, const __half* __restrict__ rawT,
    const float* __restrict__ g_sn, const float* __restrict__ be_sn,
    const float* __restrict__ g_tn, const float* __restrict__ be_tn,
    const float* __restrict__ T_t,  const float* __restrict__ t_att,
    const float* __restrict__ s_att, __half* __restrict__ T_fusion)
{
    __shared__ float sh_sa[2][NTAU][HDIM];   // 20 KB staged s_att
    __shared__ float red[8][4];
    __shared__ float sh[2][NTAU][4];

    const int tid = threadIdx.x;
    const int lane = tid & 31, w = tid >> 5;
    const int b0 = blockIdx.x * 2;
    size_t off4[2];
    off4[0] = ((size_t)b0 * HDIM) >> 2;
    off4[1] = off4[0] + (HDIM >> 2);

    // ---- PRE-WAIT: prefetch s_att (independent of upstream GEMM) ----
    {
        const uint32_t sbase = smem_u32(&sh_sa[0][0][0]);
        #pragma unroll
        for (int k = 0; k < 10; ++k) {
            const int idx = tid + k * 128;        // 0..1279 float4 chunks
            const int q  = idx / 640;
            const int t  = (idx - q * 640) >> 7;  // /128
            const int c4 = idx & 127;
            const float* src = s_att + (size_t)t * BDIM * HDIM +
                               (size_t)(b0 + q) * HDIM + c4 * 4;
            CP16(sbase + (uint32_t)(((q * NTAU + t) * HDIM + c4 * 4) * 4), src);
        }
        CP_COMMIT();
    }
    grid_dep_wait();   // block until producer GEMM complete (PDL)

    float4 vs[2], vt[2];
    #pragma unroll
    for (int q = 0; q < 2; ++q) {
        vs[q] = ld_h4(rawS, off4[q] + tid);
        vt[q] = ld_h4(rawT, off4[q] + tid);
    }

    float red8[8];
    #pragma unroll
    for (int q = 0; q < 2; ++q) {
        red8[q * 4 + 0] = vs[q].x + vs[q].y + vs[q].z + vs[q].w;
        red8[q * 4 + 1] = fmaf(vs[q].x, vs[q].x, fmaf(vs[q].y, vs[q].y,
                          fmaf(vs[q].z, vs[q].z, vs[q].w * vs[q].w)));
        red8[q * 4 + 2] = vt[q].x + vt[q].y + vt[q].z + vt[q].w;
        red8[q * 4 + 3] = fmaf(vt[q].x, vt[q].x, fmaf(vt[q].y, vt[q].y,
                          fmaf(vt[q].z, vt[q].z, vt[q].w * vt[q].w)));
    }
    #pragma unroll
    for (int o = 16; o > 0; o >>= 1)
        #pragma unroll
        for (int i = 0; i < 8; ++i)
            red8[i] += __shfl_down_sync(0xffffffffu, red8[i], o);
    if (lane == 0)
        #pragma unroll
        for (int i = 0; i < 8; ++i) red[i][w] = red8[i];
    CP_WAIT0();          // s_att staged
    __syncthreads();

    const float invN = 1.0f / (float)HDIM;
    float muS[2], rS[2], muT[2], rT[2];
    #pragma unroll
    for (int q = 0; q < 2; ++q) {
        const float sS  = red[q*4+0][0] + red[q*4+0][1] + red[q*4+0][2] + red[q*4+0][3];
        const float ssS = red[q*4+1][0] + red[q*4+1][1] + red[q*4+1][2] + red[q*4+1][3];
        const float sT  = red[q*4+2][0] + red[q*4+2][1] + red[q*4+2][2] + red[q*4+2][3];
        const float ssT = red[q*4+3][0] + red[q*4+3][1] + red[q*4+3][2] + red[q*4+3][3];
        muS[q] = sS * invN;
        rS[q]  = rsqrtf(ssS * invN - muS[q] * muS[q] + EPSV);
        muT[q] = sT * invN;
        rT[q]  = rsqrtf(ssT * invN - muT[q] * muT[q] + EPSV);
    }

    const float4 gs = reinterpret_cast<const float4*>(g_sn)[tid];
    const float4 bs = reinterpret_cast<const float4*>(be_sn)[tid];
    const float4 gt = reinterpret_cast<const float4*>(g_tn)[tid];
    const float4 bt = reinterpret_cast<const float4*>(be_tn)[tid];

    float4 sn[2], tn[2];
    #pragma unroll
    for (int q = 0; q < 2; ++q) {
        sn[q].x = (vs[q].x - muS[q]) * rS[q] * gs.x + bs.x;
        sn[q].y = (vs[q].y - muS[q]) * rS[q] * gs.y + bs.y;
        sn[q].z = (vs[q].z - muS[q]) * rS[q] * gs.z + bs.z;
        sn[q].w = (vs[q].w - muS[q]) * rS[q] * gs.w + bs.w;
        tn[q].x = (vt[q].x - muT[q]) * rT[q] * gt.x + bt.x;
        tn[q].y = (vt[q].y - muT[q]) * rT[q] * gt.y + bt.y;
        tn[q].z = (vt[q].z - muT[q]) * rT[q] * gt.z + bt.z;
        tn[q].w = (vt[q].w - muT[q]) * rT[q] * gt.w + bt.w;
    }

    float dot[2][NTAU];
    #pragma unroll
    for (int t = 0; t < NTAU; ++t)
        #pragma unroll
        for (int q = 0; q < 2; ++q) {
            const float4 sa = *reinterpret_cast<const float4*>(&sh_sa[q][t][tid * 4]);
            dot[q][t] = fmaf(sa.x, sn[q].x, fmaf(sa.y, sn[q].y,
                        fmaf(sa.z, sn[q].z, sa.w * sn[q].w)));
        }
    #pragma unroll
    for (int q = 0; q < 2; ++q)
        #pragma unroll
        for (int t = 0; t < NTAU; ++t) {
            float d = dot[q][t];
            #pragma unroll
            for (int o = 16; o > 0; o >>= 1)
                d += __shfl_down_sync(0xffffffffu, d, o);
            if (lane == 0) sh[q][t][w] = d;
        }
    __syncthreads();

    const float scale = rsqrtf((float)HDIM);
    float wt[2][NTAU];
    #pragma unroll
    for (int q = 0; q < 2; ++q) {
        float mx = -1e30f;
        #pragma unroll
        for (int t = 0; t < NTAU; ++t) {
            float v = (sh[q][t][0] + sh[q][t][1] + sh[q][t][2] + sh[q][t][3]) * scale;
            wt[q][t] = v;
            mx = fmaxf(mx, v);
        }
        float sum = 0.f;
        #pragma unroll
        for (int t = 0; t < NTAU; ++t) { wt[q][t] = expf(wt[q][t] - mx); sum += wt[q][t]; }
        const float inv = 1.0f / sum;
        #pragma unroll
        for (int t = 0; t < NTAU; ++t) wt[q][t] *= inv;
    }

    float4 trend[2] = {{0.f,0.f,0.f,0.f}, {0.f,0.f,0.f,0.f}};
    #pragma unroll
    for (int t = 0; t < NTAU; ++t) {
        const size_t tb = (size_t)t * BDIM * HDIM >> 2;
        #pragma unroll
        for (int q = 0; q < 2; ++q) {
            const float4 ta = reinterpret_cast<const float4*>(t_att)[tb + off4[q] + tid];
            trend[q].x = fmaf(wt[q][t], ta.x, trend[q].x);
            trend[q].y = fmaf(wt[q][t], ta.y, trend[q].y);
            trend[q].z = fmaf(wt[q][t], ta.z, trend[q].z);
            trend[q].w = fmaf(wt[q][t], ta.w, trend[q].w);
        }
    }

    #pragma unroll
    for (int q = 0; q < 2; ++q) {
        const float4 tt = reinterpret_cast<const float4*>(T_t)[off4[q] + tid];
        const float g0 = sigmoidf_(tn[q].x);
        const float g1 = sigmoidf_(tn[q].y);
        const float g2 = sigmoidf_(tn[q].z);
        const float g3 = sigmoidf_(tn[q].w);
        const float o0 = tt.x * g0 + (1.0f - g0) * trend[q].x;
        const float o1 = tt.y * g1 + (1.0f - g1) * trend[q].y;
        const float o2 = tt.z * g2 + (1.0f - g2) * trend[q].z;
        const float o3 = tt.w * g3 + (1.0f - g3) * trend[q].w;
        __half2* out2 = reinterpret_cast<__half2*>(T_fusion) + off4[q] * 2 + tid * 2;
        out2[0] = __floats2half2_rn(o0, o1);
        out2[1] = __floats2half2_rn(o2, o3);
    }
}

// ---------------- fused LN(1536)x2 + gate/residual, 2 rows/block, PDL -------
__global__ void __launch_bounds__(384) ln_gate_kernel(
    const __half* __restrict__ Tcat, const __half* __restrict__ Scat,
    const float* __restrict__ S_t,
    const float* __restrict__ g_t, const float* __restrict__ be_t,
    const float* __restrict__ g_s, const float* __restrict__ be_s,
    float* __restrict__ out)
{
    constexpr int N3 = 3 * HDIM;         // 1536
    const int tid = threadIdx.x;
    const int lane = tid & 31, w = tid >> 5;   // 12 warps
    const int b0 = blockIdx.x * 2;

    __shared__ float  shT[2][N3];
    __shared__ float  shS[2][N3];
    __shared__ float  red[8][12];
    __shared__ __half sh_sc[2 * N3];     // staged Scat (6 KB)
    __shared__ float  sh_st[2 * HDIM];   // staged S_t  (4 KB)

    // ---- PRE-WAIT: prefetch Scat (from earlier GEMM) + S_t (input) ----
    {
        const uint32_t sc = smem_u32(sh_sc);
        CP16(sc + (uint32_t)(tid * 16),
             (const char*)(Scat + (size_t)b0 * N3) + tid * 16);   // 384x16B
        if (tid < 256) {
            const uint32_t st = smem_u32(sh_st);
            CP16(st + (uint32_t)(tid * 16),
                 S_t + (size_t)b0 * HDIM + tid * 4);              // 256x16B
        }
        CP_COMMIT();
    }
    grid_dep_wait();   // wait for T_concat GEMM (PDL)

    float4 tv[2], sv[2];
    #pragma unroll
    for (int q = 0; q < 2; ++q)
        tv[q] = ld_h4(Tcat, (((size_t)(b0 + q) * N3) >> 2) + tid);
    CP_WAIT0();
    __syncthreads();
    #pragma unroll
    for (int q = 0; q < 2; ++q)
        sv[q] = ld_h4(sh_sc, (size_t)q * (N3 / 4) + tid);

    float red8[8];
    #pragma unroll
    for (int q = 0; q < 2; ++q) {
        red8[q * 4 + 0] = tv[q].x + tv[q].y + tv[q].z + tv[q].w;
        red8[q * 4 + 1] = fmaf(tv[q].x, tv[q].x, fmaf(tv[q].y, tv[q].y,
                          fmaf(tv[q].z, tv[q].z, tv[q].w * tv[q].w)));
        red8[q * 4 + 2] = sv[q].x + sv[q].y + sv[q].z + sv[q].w;
        red8[q * 4 + 3] = fmaf(sv[q].x, sv[q].x, fmaf(sv[q].y, sv[q].y,
                          fmaf(sv[q].z, sv[q].z, sv[q].w * sv[q].w)));
    }
    #pragma unroll
    for (int o = 16; o > 0; o >>= 1)
        #pragma unroll
        for (int i = 0; i < 8; ++i)
            red8[i] += __shfl_down_sync(0xffffffffu, red8[i], o);
    if (lane == 0)
        #pragma unroll
        for (int i = 0; i < 8; ++i) red[i][w] = red8[i];
    __syncthreads();

    const float invN = 1.0f / (float)N3;
    float muT[2], rT[2], muS[2], rS[2];
    #pragma unroll
    for (int q = 0; q < 2; ++q) {
        float tS = 0.f, tSS = 0.f, zS = 0.f, zSS = 0.f;
        #pragma unroll
        for (int i = 0; i < 12; ++i) {
            tS += red[q*4+0][i]; tSS += red[q*4+1][i];
            zS += red[q*4+2][i]; zSS += red[q*4+3][i];
        }
        muT[q] = tS * invN;
        rT[q]  = rsqrtf(tSS * invN - muT[q] * muT[q] + EPSV);
        muS[q] = zS * invN;
        rS[q]  = rsqrtf(zSS * invN - muS[q] * muS[q] + EPSV);
    }

    const float4 gt = reinterpret_cast<const float4*>(g_t)[tid];
    const float4 bt = reinterpret_cast<const float4*>(be_t)[tid];
    const float4 gs = reinterpret_cast<const float4*>(g_s)[tid];
    const float4 bs = reinterpret_cast<const float4*>(be_s)[tid];

    const int c = tid * 4;
    #pragma unroll
    for (int q = 0; q < 2; ++q) {
        shT[q][c + 0] = (tv[q].x - muT[q]) * rT[q] * gt.x + bt.x;
        shT[q][c + 1] = (tv[q].y - muT[q]) * rT[q] * gt.y + bt.y;
        shT[q][c + 2] = (tv[q].z - muT[q]) * rT[q] * gt.z + bt.z;
        shT[q][c + 3] = (tv[q].w - muT[q]) * rT[q] * gt.w + bt.w;
        shS[q][c + 0] = (sv[q].x - muS[q]) * rS[q] * gs.x + bs.x;
        shS[q][c + 1] = (sv[q].y - muS[q]) * rS[q] * gs.y + bs.y;
        shS[q][c + 2] = (sv[q].z - muS[q]) * rS[q] * gs.z + bs.z;
        shS[q][c + 3] = (sv[q].w - muS[q]) * rS[q] * gs.w + bs.w;
    }
    __syncthreads();

    #pragma unroll
    for (int q = 0; q < 2; ++q) {
        const size_t rowoff = (size_t)(b0 + q) * HDIM;
        for (int j = tid; j < HDIM; j += 384) {
            const float tg = sigmoidf_(shT[q][j]);
            const float sg = sigmoidf_(shS[q][j]);
            const float T_new = tg * shT[q][HDIM + j] + (1.0f - tg) * shS[q][HDIM + j];
            const float S_new = sg * shS[q][2 * HDIM + j] + (1.0f - sg) * shT[q][2 * HDIM + j]
                              + sh_st[q * HDIM + j];
            out[rowoff + j] = T_new;
            out[(size_t)BDIM * HDIM + rowoff + j] = S_new;
        }
    }
}

// ---------------- launch -----------------------------------------------------
extern "C" void kernel_launch(void* const* d_in, const int* in_sizes, int n_in,
                              void* d_out, int out_size)
{
    const float* T_t   = (const float*)d_in[0];
    const float* S_t   = (const float*)d_in[1];
    const float* t_att = (const float*)d_in[2];
    const float* s_att = (const float*)d_in[3];
    const float* W_tn  = (const float*)d_in[4];
    const float* b_tn  = (const float*)d_in[5];
    const float* g_tn  = (const float*)d_in[6];
    const float* be_tn = (const float*)d_in[7];
    const float* W_sn  = (const float*)d_in[8];
    const float* b_sn  = (const float*)d_in[9];
    const float* g_sn  = (const float*)d_in[10];
    const float* be_sn = (const float*)d_in[11];
    const float* W_t   = (const float*)d_in[12];
    const float* b_t   = (const float*)d_in[13];
    const float* g_t   = (const float*)d_in[14];
    const float* be_t  = (const float*)d_in[15];
    const float* W_s   = (const float*)d_in[16];
    const float* b_s   = (const float*)d_in[17];
    const float* g_s   = (const float*)d_in[18];
    const float* be_s  = (const float*)d_in[19];
    float* out = (float*)d_out;

    __half *bufT, *bufS, *rawS, *rawT, *tfus, *Tr, *Sr;
    __half *Wtn_t, *Wsn_t, *Wt_t, *Ws_t;
    cudaGetSymbolAddress((void**)&bufT,  g_bufT);
    cudaGetSymbolAddress((void**)&bufS,  g_bufS);
    cudaGetSymbolAddress((void**)&rawS,  g_rawS);
    cudaGetSymbolAddress((void**)&rawT,  g_rawT);
    cudaGetSymbolAddress((void**)&tfus,  g_tfus);
    cudaGetSymbolAddress((void**)&Tr,    g_Tr);
    cudaGetSymbolAddress((void**)&Sr,    g_Sr);
    cudaGetSymbolAddress((void**)&Wtn_t, g_Wtn_t);
    cudaGetSymbolAddress((void**)&Wsn_t, g_Wsn_t);
    cudaGetSymbolAddress((void**)&Wt_t,  g_Wt_t);
    cudaGetSymbolAddress((void**)&Ws_t,  g_Ws_t);

    const int GEMM_SMEM = 3 * 20480;   // 61440 B (3 stages, BK=32)
    cudaFuncSetAttribute(gemm_f16, cudaFuncAttributeMaxDynamicSharedMemorySize,
                         GEMM_SMEM);
    cudaFuncSetAttribute(gemm3_f16, cudaFuncAttributeMaxDynamicSharedMemorySize,
                         GEMM_SMEM);

    // ---- merged prepass (1 launch) ----
    prep_all<<<dim3(48, 16, 6), dim3(32, 32)>>>(
        W_sn, W_tn, W_t, W_s, S_t, T_t,
        Wsn_t, Wtn_t, Wt_t, Ws_t, Sr, Tr);

    // ---- 3 independent GEMMs in one flat launch (S_concat, rawS, rawT) ----
    gemm3_f16<<<2560, 256, GEMM_SMEM>>>(
        Sr, Tr, Wsn_t, Wtn_t, Ws_t, b_sn, b_tn, b_s, rawS, rawT, bufS);

    // PDL launch attribute (downstream kernels may launch before producer
    // finishes; griddepcontrol.wait provides the ordering)
    cudaLaunchAttribute pdl[1];
    pdl[0].id = cudaLaunchAttributeProgrammaticStreamSerialization;
    pdl[0].val.programmaticStreamSerializationAllowed = 1;

    // fused LN + LN + attention + fusion gate (2 rows/block) — PDL edge
    {
        cudaLaunchConfig_t cfg = {};
        cfg.gridDim  = dim3(BDIM / 2);
        cfg.blockDim = dim3(128);
        cfg.attrs = pdl;
        cfg.numAttrs = 1;
        cudaLaunchKernelEx(&cfg, ln2_attn_fusion,
                           (const __half*)rawS, (const __half*)rawT,
                           g_sn, be_sn, g_tn, be_tn, T_t, t_att, s_att,
                           (__half*)tfus);
    }
    // T_concat raw (fp16)
    gemm_f16<<<dim3(12, 128), 256, GEMM_SMEM>>>(tfus, Wt_t, b_t, bufT, 3 * HDIM);
    // fused LN + LN + gate + residual -> out (2 rows/block) — PDL edge
    {
        cudaLaunchConfig_t cfg = {};
        cfg.gridDim  = dim3(BDIM / 2);
        cfg.blockDim = dim3(384);
        cfg.attrs = pdl;
        cfg.numAttrs = 1;
        cudaLaunchKernelEx(&cfg, ln_gate_kernel,
                           (const __half*)bufT, (const __half*)bufS, S_t,
                           g_t, be_t, g_s, be_s, out);
    }
}